// round 3
// baseline (speedup 1.0000x reference)
#include <cuda_runtime.h>
#include <math.h>

#define B_    32
#define EMB_  256
#define HID_  516
#define G4_   2064     // 4*HID_
#define SRC_  64
#define DEC_  64
#define V_    32000
#define ROWS_ 2048     // DEC_*B_

// ---------------- scratch (static device globals; no allocation) ----------------
__device__ float g_pre[2][SRC_ * B_ * G4_];   // [enc,dec] input-proj + bias, per step
__device__ float g_h0[2][B_ * HID_];          // double-buffered layer0 h
__device__ float g_h1[2][B_ * HID_];          // double-buffered layer1 h
__device__ float g_c0[B_ * HID_];
__device__ float g_c1[B_ * HID_];
__device__ float g_hist[DEC_ * B_ * HID_];    // decoder layer1 h history
__device__ float g_sumexp[ROWS_];
__device__ float g_tgt[ROWS_];

// ---------------- init: zero states + reduction buffers ----------------
__global__ void init_kernel() {
    int stride = gridDim.x * blockDim.x;
    for (int i = blockIdx.x * blockDim.x + threadIdx.x; i < B_ * HID_; i += stride) {
        g_h0[0][i] = 0.f; g_h0[1][i] = 0.f;
        g_h1[0][i] = 0.f; g_h1[1][i] = 0.f;
        g_c0[i] = 0.f;    g_c1[i] = 0.f;
    }
    for (int i = blockIdx.x * blockDim.x + threadIdx.x; i < ROWS_; i += stride) {
        g_sumexp[i] = 0.f; g_tgt[i] = 0.f;
    }
}

// ---------------- precompute: pre[t,b,col] = bias + emb[idx[t,b]] @ Wih^T ----------------
// grid (129, 64), block 128. Block: one timestep t, 4 hidden cols (x4 gates).
__global__ __launch_bounds__(128) void pre_kernel(
    const int* __restrict__ idx, const float* __restrict__ emb,
    const float* __restrict__ Wih, const float* __restrict__ b1,
    const float* __restrict__ b2, int which)
{
    const int t   = blockIdx.y;
    const int jb  = blockIdx.x;              // 0..128
    const int tid = threadIdx.x;
    const int b   = tid & 31;
    const int jl  = tid >> 5;                // 0..3
    const int j   = jb * 4 + jl;             // 0..515

    __shared__ int   sidx[B_];
    __shared__ float us[B_][65];
    __shared__ float ws[4][4][64];

    if (tid < B_) sidx[tid] = idx[t * B_ + tid];
    __syncthreads();

    float acc0 = 0.f, acc1 = 0.f, acc2 = 0.f, acc3 = 0.f;

    for (int k0 = 0; k0 < EMB_; k0 += 64) {
        #pragma unroll
        for (int i = 0; i < 16; i++) {
            int lin = tid + 128 * i;
            int rr = lin >> 6, kk = lin & 63;
            us[rr][kk] = emb[sidx[rr] * EMB_ + k0 + kk];
        }
        #pragma unroll
        for (int i = 0; i < 8; i++) {
            int lin = tid + 128 * i;
            int g = lin >> 8, r2 = lin & 255, jw = r2 >> 6, kk = r2 & 63;
            ws[g][jw][kk] = Wih[(g * HID_ + jb * 4 + jw) * EMB_ + k0 + kk];
        }
        __syncthreads();
        #pragma unroll
        for (int kk = 0; kk < 64; kk++) {
            float uv = us[b][kk];
            acc0 = fmaf(uv, ws[0][jl][kk], acc0);
            acc1 = fmaf(uv, ws[1][jl][kk], acc1);
            acc2 = fmaf(uv, ws[2][jl][kk], acc2);
            acc3 = fmaf(uv, ws[3][jl][kk], acc3);
        }
        __syncthreads();
    }

    float* o = &g_pre[which][(t * B_ + b) * G4_];
    o[0 * HID_ + j] = acc0 + b1[0 * HID_ + j] + b2[0 * HID_ + j];
    o[1 * HID_ + j] = acc1 + b1[1 * HID_ + j] + b2[1 * HID_ + j];
    o[2 * HID_ + j] = acc2 + b1[2 * HID_ + j] + b2[2 * HID_ + j];
    o[3 * HID_ + j] = acc3 + b1[3 * HID_ + j] + b2[3 * HID_ + j];
}

// ---------------- sequential LSTM step ----------------
struct LayerArgs {
    const float* Wx;     // layer1: Wih1 (null for layer0)
    const float* Wh;     // Whh
    const float* bias1;  // layer1 only
    const float* bias2;
    int layer;           // 0 or 1
    int parity;          // p for this step (reads h[p], writes h[p^1])
    int pre_sel;         // 0 enc / 1 dec (layer0)
    int tstep;           // step index within enc/dec
    int hist;            // layer1 decoder: write history
    int valid;
};
struct DualArgs { LayerArgs a0, a1; };

__device__ __forceinline__ float sigf(float x) { return 1.f / (1.f + __expf(-x)); }

__device__ void layer_body(const LayerArgs a, int jb) {
    const int tid = threadIdx.x;
    const int b   = tid & 31;
    const int jl  = tid >> 5;
    const int j   = jb * 4 + jl;

    __shared__ float us[B_][65];
    __shared__ float ws[4][4][64];

    float acc0 = 0.f, acc1 = 0.f, acc2 = 0.f, acc3 = 0.f;
    const int p = a.parity;
    const float* xin = a.layer ? g_h0[p ^ 1] : (const float*)nullptr;
    const float* hin = a.layer ? g_h1[p]     : g_h0[p];

    for (int seg = 0; seg < 2; seg++) {
        const float* vec = seg ? hin  : xin;
        const float* W   = seg ? a.Wh : a.Wx;
        if (vec == nullptr) continue;
        for (int k0 = 0; k0 < HID_; k0 += 64) {
            #pragma unroll
            for (int i = 0; i < 16; i++) {
                int lin = tid + 128 * i;
                int rr = lin >> 6, kk = lin & 63;
                us[rr][kk] = (k0 + kk < HID_) ? vec[rr * HID_ + k0 + kk] : 0.f;
            }
            #pragma unroll
            for (int i = 0; i < 8; i++) {
                int lin = tid + 128 * i;
                int g = lin >> 8, r2 = lin & 255, jw = r2 >> 6, kk = r2 & 63;
                ws[g][jw][kk] = (k0 + kk < HID_)
                    ? W[(g * HID_ + jb * 4 + jw) * HID_ + k0 + kk] : 0.f;
            }
            __syncthreads();
            #pragma unroll
            for (int kk = 0; kk < 64; kk++) {
                float uv = us[b][kk];
                acc0 = fmaf(uv, ws[0][jl][kk], acc0);
                acc1 = fmaf(uv, ws[1][jl][kk], acc1);
                acc2 = fmaf(uv, ws[2][jl][kk], acc2);
                acc3 = fmaf(uv, ws[3][jl][kk], acc3);
            }
            __syncthreads();
        }
    }

    if (a.layer == 0) {
        const float* pre = &g_pre[a.pre_sel][(a.tstep * B_ + b) * G4_];
        acc0 += pre[0 * HID_ + j];
        acc1 += pre[1 * HID_ + j];
        acc2 += pre[2 * HID_ + j];
        acc3 += pre[3 * HID_ + j];
    } else {
        acc0 += a.bias1[0 * HID_ + j] + a.bias2[0 * HID_ + j];
        acc1 += a.bias1[1 * HID_ + j] + a.bias2[1 * HID_ + j];
        acc2 += a.bias1[2 * HID_ + j] + a.bias2[2 * HID_ + j];
        acc3 += a.bias1[3 * HID_ + j] + a.bias2[3 * HID_ + j];
    }

    float* cst  = a.layer ? g_c1 : g_c0;
    float* hout = a.layer ? g_h1[p ^ 1] : g_h0[p ^ 1];

    float c  = cst[b * HID_ + j];
    float iv = sigf(acc0), fv = sigf(acc1);
    float gv = tanhf(acc2), ov = sigf(acc3);
    c = fv * c + iv * gv;
    cst[b * HID_ + j] = c;
    float h = ov * tanhf(c);
    hout[b * HID_ + j] = h;
    if (a.hist) g_hist[(a.tstep * B_ + b) * HID_ + j] = h;
}

// grid (129, 2): y==0 -> layer1(step s-1), y==1 -> layer0(step s)
__global__ __launch_bounds__(128) void dual_step_kernel(DualArgs d) {
    LayerArgs a = blockIdx.y ? d.a1 : d.a0;
    if (!a.valid) return;
    layer_body(a, blockIdx.x);
}

// ---------------- fused vocab projection + log-sum-exp CE ----------------
// grid (250, 64): block tile = 32 rows (one decoder timestep) x 128 vocab, K=516.
// Logits are small (|x| < ~0.6), so sum-exp without max subtraction is exact enough.
__global__ __launch_bounds__(256) void ce_kernel(
    const float* __restrict__ Wout, const float* __restrict__ bout,
    const int* __restrict__ y)
{
    const int t    = blockIdx.y;
    const int v0   = blockIdx.x * 128;
    const int tid  = threadIdx.x;
    const int lane = tid & 31;   // vocab group within warp
    const int rg   = tid >> 5;   // row group 0..7 (warp id)

    __shared__ float As[32][17];
    __shared__ float Bs[128][17];

    float acc[4][4];
    #pragma unroll
    for (int i = 0; i < 4; i++)
        #pragma unroll
        for (int jj = 0; jj < 4; jj++) acc[i][jj] = 0.f;

    const float* Hb = &g_hist[t * B_ * HID_];

    for (int k0 = 0; k0 < HID_; k0 += 16) {
        #pragma unroll
        for (int i = 0; i < 2; i++) {
            int lin = tid + 256 * i;
            int rr = lin >> 4, kk = lin & 15;
            As[rr][kk] = (k0 + kk < HID_) ? Hb[rr * HID_ + k0 + kk] : 0.f;
        }
        #pragma unroll
        for (int i = 0; i < 8; i++) {
            int lin = tid + 256 * i;
            int vv = lin >> 4, kk = lin & 15;
            Bs[vv][kk] = (k0 + kk < HID_) ? Wout[(v0 + vv) * HID_ + k0 + kk] : 0.f;
        }
        __syncthreads();
        #pragma unroll
        for (int kk = 0; kk < 16; kk++) {
            float a0 = As[rg * 4 + 0][kk], a1 = As[rg * 4 + 1][kk];
            float a2 = As[rg * 4 + 2][kk], a3 = As[rg * 4 + 3][kk];
            float b0 = Bs[lane][kk],       b1v = Bs[lane + 32][kk];
            float b2v = Bs[lane + 64][kk], b3v = Bs[lane + 96][kk];
            acc[0][0] = fmaf(a0, b0, acc[0][0]); acc[0][1] = fmaf(a0, b1v, acc[0][1]);
            acc[0][2] = fmaf(a0, b2v, acc[0][2]); acc[0][3] = fmaf(a0, b3v, acc[0][3]);
            acc[1][0] = fmaf(a1, b0, acc[1][0]); acc[1][1] = fmaf(a1, b1v, acc[1][1]);
            acc[1][2] = fmaf(a1, b2v, acc[1][2]); acc[1][3] = fmaf(a1, b3v, acc[1][3]);
            acc[2][0] = fmaf(a2, b0, acc[2][0]); acc[2][1] = fmaf(a2, b1v, acc[2][1]);
            acc[2][2] = fmaf(a2, b2v, acc[2][2]); acc[2][3] = fmaf(a2, b3v, acc[2][3]);
            acc[3][0] = fmaf(a3, b0, acc[3][0]); acc[3][1] = fmaf(a3, b1v, acc[3][1]);
            acc[3][2] = fmaf(a3, b2v, acc[3][2]); acc[3][3] = fmaf(a3, b3v, acc[3][3]);
        }
        __syncthreads();
    }

    #pragma unroll
    for (int i = 0; i < 4; i++) {
        int brow = rg * 4 + i;
        int r    = t * 32 + brow;
        int tgt  = y[(t + 1) * 32 + brow];
        float rs = 0.f;
        #pragma unroll
        for (int jj = 0; jj < 4; jj++) {
            int v = v0 + lane + 32 * jj;
            float logit = acc[i][jj] + bout[v];
            rs += __expf(logit);
            if (v == tgt) atomicAdd(&g_tgt[r], logit);
        }
        #pragma unroll
        for (int off = 16; off; off >>= 1)
            rs += __shfl_xor_sync(0xffffffffu, rs, off);
        if (lane == 0) atomicAdd(&g_sumexp[r], rs);
    }
}

// ---------------- final reduction ----------------
__global__ __launch_bounds__(256) void finalize_kernel(float* out) {
    __shared__ float sm[256];
    float s = 0.f;
    for (int r = threadIdx.x; r < ROWS_; r += 256)
        s += logf(g_sumexp[r]) - g_tgt[r];
    sm[threadIdx.x] = s;
    __syncthreads();
    for (int st = 128; st; st >>= 1) {
        if (threadIdx.x < st) sm[threadIdx.x] += sm[threadIdx.x + st];
        __syncthreads();
    }
    if (threadIdx.x == 0) out[0] = sm[0] / 32.f;
}

// ---------------- host launcher ----------------
extern "C" void kernel_launch(void* const* d_in, const int* in_sizes, int n_in,
                              void* d_out, int out_size)
{
    (void)in_sizes; (void)n_in; (void)out_size;
    const int*   x        = (const int*)  d_in[0];
    const int*   y        = (const int*)  d_in[1];
    const float* encemb   = (const float*)d_in[2];
    const float* decemb   = (const float*)d_in[3];
    const float* enc_Wih0 = (const float*)d_in[4];
    const float* enc_Whh0 = (const float*)d_in[5];
    const float* enc_bih0 = (const float*)d_in[6];
    const float* enc_bhh0 = (const float*)d_in[7];
    const float* enc_Wih1 = (const float*)d_in[8];
    const float* enc_Whh1 = (const float*)d_in[9];
    const float* enc_bih1 = (const float*)d_in[10];
    const float* enc_bhh1 = (const float*)d_in[11];
    const float* dec_Wih0 = (const float*)d_in[12];
    const float* dec_Whh0 = (const float*)d_in[13];
    const float* dec_bih0 = (const float*)d_in[14];
    const float* dec_bhh0 = (const float*)d_in[15];
    const float* dec_Wih1 = (const float*)d_in[16];
    const float* dec_Whh1 = (const float*)d_in[17];
    const float* dec_bih1 = (const float*)d_in[18];
    const float* dec_bhh1 = (const float*)d_in[19];
    const float* Wout     = (const float*)d_in[20];
    const float* bout     = (const float*)d_in[21];
    float* out = (float*)d_out;

    init_kernel<<<64, 256>>>();

    // parallel input projections (enc + dec) — independent of the scan
    pre_kernel<<<dim3(129, 64), 128>>>(x, encemb, enc_Wih0, enc_bih0, enc_bhh0, 0);
    pre_kernel<<<dim3(129, 64), 128>>>(y, decemb, dec_Wih0, dec_bih0, dec_bhh0, 1);

    // sequential scan: 129 dual slots; slot s runs layer1(s-1) and layer0(s)
    for (int s = 0; s <= 128; s++) {
        DualArgs d;
        d.a0 = LayerArgs{}; d.a1 = LayerArgs{};
        if (s >= 1) {                        // layer1 of step z = s-1
            int z = s - 1;
            int sel = (z < 64) ? 0 : 1;
            d.a0.layer  = 1;
            d.a0.parity = z & 1;
            d.a0.Wx     = sel ? dec_Wih1 : enc_Wih1;
            d.a0.Wh     = sel ? dec_Whh1 : enc_Whh1;
            d.a0.bias1  = sel ? dec_bih1 : enc_bih1;
            d.a0.bias2  = sel ? dec_bhh1 : enc_bhh1;
            d.a0.pre_sel = sel;
            d.a0.tstep  = sel ? (z - 64) : z;
            d.a0.hist   = (z >= 64) ? 1 : 0;
            d.a0.valid  = 1;
        }
        if (s <= 127) {                      // layer0 of step s
            int sel = (s < 64) ? 0 : 1;
            d.a1.layer  = 0;
            d.a1.parity = s & 1;
            d.a1.Wx     = nullptr;
            d.a1.Wh     = sel ? dec_Whh0 : enc_Whh0;
            d.a1.bias1  = nullptr;
            d.a1.bias2  = nullptr;
            d.a1.pre_sel = sel;
            d.a1.tstep  = sel ? (s - 64) : s;
            d.a1.hist   = 0;
            d.a1.valid  = 1;
        }
        dual_step_kernel<<<dim3(129, 2), 128>>>(d);
    }

    // fused vocab projection + CE reductions
    ce_kernel<<<dim3(250, 64), 256>>>(Wout, bout, y);

    finalize_kernel<<<1, 256>>>(out);
}

// round 4
// speedup vs baseline: 2.5570x; 2.5570x over previous
#include <cuda_runtime.h>
#include <cuda_bf16.h>
#include <math.h>

#define B_    32
#define EMB_  256
#define HID_  516
#define G4_   2064     // 4*HID_
#define SRC_  64
#define DEC_  64
#define V_    32000
#define ROWS_ 2048     // DEC_*B_
#define NK_   528      // K padded to multiple of 16
#define NKI_  33       // k-iterations of 16
#define SROW_ 536      // smem row stride (bf16 elems) - bank-conflict-free for ldmatrix
#define NPAD_ 2112     // gate-col dimension padded (33 blocks * 64)

// ---------------- scratch (static device globals; no allocation) ----------------
__device__ __nv_bfloat16 g_Wb[6][NPAD_ * NK_];        // scan weights, bf16, gate-interleaved [j*4+g][k]
__device__ __nv_bfloat16 g_Woutb[V_ * NK_];           // Wout bf16 padded
__device__ float         g_pre[2][SRC_ * B_ * G4_];   // input proj + biases, gate-interleaved
__device__ __nv_bfloat16 g_hb[2][2][B_ * NK_];        // h state [layer][parity], bf16, k-padded
__device__ float         g_c[2][B_ * HID_];           // c state fp32
__device__ __nv_bfloat16 g_histb[DEC_ * B_ * NK_];    // decoder h1 history, bf16
__device__ float         g_biasI[2][G4_];             // layer1 bias, gate-interleaved
__device__ float         g_sumexp[ROWS_];
__device__ float         g_tgt[ROWS_];

// ---------------- helpers ----------------
__device__ __forceinline__ unsigned smem_u32(const void* p) {
    return (unsigned)__cvta_generic_to_shared(p);
}
__device__ __forceinline__ void ldsm4(unsigned a[4], unsigned addr) {
    asm volatile("ldmatrix.sync.aligned.m8n8.x4.shared.b16 {%0,%1,%2,%3}, [%4];"
        : "=r"(a[0]), "=r"(a[1]), "=r"(a[2]), "=r"(a[3]) : "r"(addr));
}
__device__ __forceinline__ void mma_bf16(float c[4], const unsigned a[4], unsigned b0, unsigned b1) {
    asm volatile("mma.sync.aligned.m16n8k16.row.col.f32.bf16.bf16.f32 "
        "{%0,%1,%2,%3},{%4,%5,%6,%7},{%8,%9},{%0,%1,%2,%3};"
        : "+f"(c[0]), "+f"(c[1]), "+f"(c[2]), "+f"(c[3])
        : "r"(a[0]), "r"(a[1]), "r"(a[2]), "r"(a[3]), "r"(b0), "r"(b1));
}
__device__ __forceinline__ float sigf(float x) { return 1.f / (1.f + __expf(-x)); }

// ---------------- init: zero states + reduction buffers + hist ----------------
__global__ void init_kernel() {
    const int stride = gridDim.x * blockDim.x;
    const int i0 = blockIdx.x * blockDim.x + threadIdx.x;
    const __nv_bfloat16 z = __float2bfloat16(0.f);
    for (int i = i0; i < B_ * NK_; i += stride) {
        g_hb[0][0][i] = z; g_hb[0][1][i] = z;
        g_hb[1][0][i] = z; g_hb[1][1][i] = z;
    }
    for (int i = i0; i < B_ * HID_; i += stride) { g_c[0][i] = 0.f; g_c[1][i] = 0.f; }
    for (int i = i0; i < ROWS_; i += stride)     { g_sumexp[i] = 0.f; g_tgt[i] = 0.f; }
    for (int i = i0; i < DEC_ * B_ * NK_; i += stride) g_histb[i] = z;
}

// ---------------- weight conversion: fp32 [4*HID][HID] -> bf16 interleaved [NPAD][NK] ----------------
__global__ __launch_bounds__(256) void conv_gate(const float* __restrict__ src, int slot) {
    int idx = blockIdx.x * blockDim.x + threadIdx.x;
    if (idx >= NPAD_ * NK_) return;
    int n = idx / NK_, k = idx - n * NK_;
    float v = 0.f;
    if (n < G4_ && k < HID_) {
        int j = n >> 2, g = n & 3;
        v = src[(g * HID_ + j) * HID_ + k];
    }
    g_Wb[slot][idx] = __float2bfloat16(v);
}

__global__ __launch_bounds__(256) void conv_wout(const float* __restrict__ src) {
    int idx = blockIdx.x * blockDim.x + threadIdx.x;
    if (idx >= V_ * NK_) return;
    int n = idx / NK_, k = idx - n * NK_;
    float v = (k < HID_) ? src[n * HID_ + k] : 0.f;
    g_Woutb[idx] = __float2bfloat16(v);
}

__global__ __launch_bounds__(256) void bias_kernel(
    const float* __restrict__ bie, const float* __restrict__ bhe,
    const float* __restrict__ bid, const float* __restrict__ bhd)
{
    int t = blockIdx.x * blockDim.x + threadIdx.x;
    if (t >= 2 * G4_) return;
    int sel = t / G4_, n = t - sel * G4_;
    int j = n >> 2, g = n & 3;
    const float* b1 = sel ? bid : bie;
    const float* b2 = sel ? bhd : bhe;
    g_biasI[sel][n] = b1[g * HID_ + j] + b2[g * HID_ + j];
}

// ---------------- precompute: pre[t,b,(j*4+g)] = bias + emb[idx[t,b]] @ Wih^T  (fp32) ----------------
__global__ __launch_bounds__(128) void pre_kernel(
    const int* __restrict__ idx, const float* __restrict__ emb,
    const float* __restrict__ Wih, const float* __restrict__ b1,
    const float* __restrict__ b2, int which)
{
    const int t   = blockIdx.y;
    const int jb  = blockIdx.x;              // 0..128
    const int tid = threadIdx.x;
    const int b   = tid & 31;
    const int jl  = tid >> 5;                // 0..3
    const int j   = jb * 4 + jl;             // 0..515

    __shared__ int   sidx[B_];
    __shared__ float us[B_][65];
    __shared__ float ws[4][4][64];

    if (tid < B_) sidx[tid] = idx[t * B_ + tid];
    __syncthreads();

    float acc0 = 0.f, acc1 = 0.f, acc2 = 0.f, acc3 = 0.f;

    for (int k0 = 0; k0 < EMB_; k0 += 64) {
        #pragma unroll
        for (int i = 0; i < 16; i++) {
            int lin = tid + 128 * i;
            int rr = lin >> 6, kk = lin & 63;
            us[rr][kk] = emb[sidx[rr] * EMB_ + k0 + kk];
        }
        #pragma unroll
        for (int i = 0; i < 8; i++) {
            int lin = tid + 128 * i;
            int g = lin >> 8, r2 = lin & 255, jw = r2 >> 6, kk = r2 & 63;
            ws[g][jw][kk] = Wih[(g * HID_ + jb * 4 + jw) * EMB_ + k0 + kk];
        }
        __syncthreads();
        #pragma unroll
        for (int kk = 0; kk < 64; kk++) {
            float uv = us[b][kk];
            acc0 = fmaf(uv, ws[0][jl][kk], acc0);
            acc1 = fmaf(uv, ws[1][jl][kk], acc1);
            acc2 = fmaf(uv, ws[2][jl][kk], acc2);
            acc3 = fmaf(uv, ws[3][jl][kk], acc3);
        }
        __syncthreads();
    }

    float4 o4;
    o4.x = acc0 + b1[0 * HID_ + j] + b2[0 * HID_ + j];
    o4.y = acc1 + b1[1 * HID_ + j] + b2[1 * HID_ + j];
    o4.z = acc2 + b1[2 * HID_ + j] + b2[2 * HID_ + j];
    o4.w = acc3 + b1[3 * HID_ + j] + b2[3 * HID_ + j];
    *(float4*)&g_pre[which][(t * B_ + b) * G4_ + j * 4] = o4;
}

// ---------------- sequential dual LSTM step via bf16 mma ----------------
struct StepArgs { int layer, sel, parity, tstep, hist, valid; };
struct Dual2 { StepArgs s0, s1; };

// grid (33, 2), block 256 (8 warps). Warp tile: M=32 (2 m16) x N=8. Block N=64.
__global__ __launch_bounds__(256) void dual_mma(Dual2 d) {
    StepArgs a = blockIdx.y ? d.s1 : d.s0;
    if (!a.valid) return;
    extern __shared__ unsigned short sA[];   // [nseg][32][SROW_]
    const int tid = threadIdx.x;
    const int lane = tid & 31, warp = tid >> 5;
    const int nseg = a.layer ? 2 : 1;

    // stage A segment(s) into smem
    {
        const unsigned* s0 = (const unsigned*)(a.layer ? g_hb[0][a.parity ^ 1] : g_hb[0][a.parity]);
        const unsigned* s1 = a.layer ? (const unsigned*)g_hb[1][a.parity] : (const unsigned*)0;
        for (int sg = 0; sg < nseg; sg++) {
            const unsigned* src = sg ? s1 : s0;
            unsigned* dst = (unsigned*)(sA + sg * B_ * SROW_);
            for (int idx = tid; idx < B_ * (NK_ / 2); idx += 256) {
                int r = idx / (NK_ / 2), w = idx - r * (NK_ / 2);
                dst[r * (SROW_ / 2) + w] = src[idx];
            }
        }
    }
    __syncthreads();

    const __nv_bfloat16* W0 = a.layer ? g_Wb[a.sel * 3 + 1] : g_Wb[a.sel * 3 + 0];
    const __nv_bfloat16* W1 = a.layer ? g_Wb[a.sel * 3 + 2] : (const __nv_bfloat16*)0;

    const int nw = blockIdx.x * 64 + warp * 8;
    float acc[2][4] = {{0.f,0.f,0.f,0.f},{0.f,0.f,0.f,0.f}};

    const unsigned sb = smem_u32(sA);
    const unsigned a_lane_off =
        ((unsigned)((lane & 7) + ((lane >> 3) & 1) * 8) * SROW_ + (unsigned)(lane >> 4) * 8) * 2;

    for (int sg = 0; sg < nseg; sg++) {
        const unsigned short* Wp = (const unsigned short*)(sg ? W1 : W0)
            + (unsigned)(nw + (lane >> 2)) * NK_ + (unsigned)((lane & 3) * 2);
        const unsigned abase = sb + (unsigned)sg * B_ * SROW_ * 2 + a_lane_off;
        #pragma unroll 4
        for (int ki = 0; ki < NKI_; ki++) {
            const int k0 = ki * 16;
            unsigned av0[4], av1[4];
            ldsm4(av0, abase + (unsigned)k0 * 2);
            ldsm4(av1, abase + (unsigned)(16 * SROW_ + k0) * 2);
            unsigned b0 = *(const unsigned*)(Wp + k0);
            unsigned b1 = *(const unsigned*)(Wp + k0 + 8);
            mma_bf16(acc[0], av0, b0, b1);
            mma_bf16(acc[1], av1, b0, b1);
        }
    }

    // epilogue: lane-pair exchange reassembles (i,f,g,o) per hidden unit
    float ex[2][4];
    #pragma unroll
    for (int mt = 0; mt < 2; mt++)
        #pragma unroll
        for (int r = 0; r < 4; r++)
            ex[mt][r] = __shfl_xor_sync(0xffffffffu, acc[mt][r], 1);

    const int cn = nw + (lane & 3) * 2;
    if (!(lane & 1) && cn < G4_) {
        const int j = cn >> 2;
        float* cst = g_c[a.layer];
        __nv_bfloat16* hout = g_hb[a.layer][a.parity ^ 1];
        #pragma unroll
        for (int mt = 0; mt < 2; mt++) {
            #pragma unroll
            for (int half = 0; half < 2; half++) {
                const int b = (lane >> 2) + mt * 16 + half * 8;
                const float ip = acc[mt][half * 2 + 0];
                const float fp = acc[mt][half * 2 + 1];
                const float gp = ex[mt][half * 2 + 0];
                const float op = ex[mt][half * 2 + 1];
                float4 add = a.layer
                    ? *(const float4*)&g_biasI[a.sel][cn]
                    : *(const float4*)&g_pre[a.sel][(a.tstep * B_ + b) * G4_ + cn];
                float iv = sigf(ip + add.x);
                float fv = sigf(fp + add.y);
                float gv = tanhf(gp + add.z);
                float ov = sigf(op + add.w);
                float c = cst[b * HID_ + j];
                c = fv * c + iv * gv;
                cst[b * HID_ + j] = c;
                float h = ov * tanhf(c);
                __nv_bfloat16 hb = __float2bfloat16(h);
                hout[b * NK_ + j] = hb;
                if (a.hist) g_histb[(a.tstep * B_ + b) * NK_ + j] = hb;
            }
        }
    }
}

// ---------------- fused vocab projection + CE via bf16 mma ----------------
// grid (250, 32), block 256 (8 warps = 2 M-groups x 4 N-groups). Block tile 64x128.
__global__ __launch_bounds__(256) void ce_mma(const int* __restrict__ y,
                                              const float* __restrict__ bout) {
    extern __shared__ unsigned short sA[];  // [64][SROW_]
    const int tid = threadIdx.x, lane = tid & 31, warp = tid >> 5;
    const int by = blockIdx.y, bx = blockIdx.x;

    // stage 64 hist rows into smem
    {
        const unsigned* src = (const unsigned*)g_histb + (unsigned)by * 64 * (NK_ / 2);
        unsigned* dst = (unsigned*)sA;
        for (int idx = tid; idx < 64 * (NK_ / 2); idx += 256) {
            int r = idx / (NK_ / 2), w = idx - r * (NK_ / 2);
            dst[r * (SROW_ / 2) + w] = src[idx];
        }
    }
    __syncthreads();

    const int wm = warp >> 2, wn = warp & 3;
    float acc[2][4][4];
    #pragma unroll
    for (int mt = 0; mt < 2; mt++)
        #pragma unroll
        for (int nt = 0; nt < 4; nt++)
            #pragma unroll
            for (int r = 0; r < 4; r++) acc[mt][nt][r] = 0.f;

    const unsigned sb = smem_u32(sA);
    const unsigned a_lane_off =
        ((unsigned)((lane & 7) + ((lane >> 3) & 1) * 8) * SROW_ + (unsigned)(lane >> 4) * 8) * 2;
    const unsigned short* Wp = (const unsigned short*)g_Woutb
        + (unsigned)(bx * 128 + wn * 32 + (lane >> 2)) * NK_ + (unsigned)((lane & 3) * 2);

    #pragma unroll 3
    for (int ki = 0; ki < NKI_; ki++) {
        const int k0 = ki * 16;
        unsigned av[2][4];
        #pragma unroll
        for (int mt = 0; mt < 2; mt++)
            ldsm4(av[mt], sb + a_lane_off + (unsigned)((wm * 32 + mt * 16) * SROW_ + k0) * 2);
        unsigned bv[4][2];
        #pragma unroll
        for (int nt = 0; nt < 4; nt++) {
            bv[nt][0] = *(const unsigned*)(Wp + nt * 8 * NK_ + k0);
            bv[nt][1] = *(const unsigned*)(Wp + nt * 8 * NK_ + k0 + 8);
        }
        #pragma unroll
        for (int mt = 0; mt < 2; mt++)
            #pragma unroll
            for (int nt = 0; nt < 4; nt++)
                mma_bf16(acc[mt][nt], av[mt], bv[nt][0], bv[nt][1]);
    }

    // epilogue: per-row sum(exp(logit)) + target logit
    #pragma unroll
    for (int mt = 0; mt < 2; mt++) {
        const int r0 = by * 64 + wm * 32 + mt * 16 + (lane >> 2);
        const int r1 = r0 + 8;
        const int tg0 = y[r0 + 32];     // y[(t+1)*32 + b] == y[row + 32]
        const int tg1 = y[r1 + 32];
        float s0 = 0.f, s1 = 0.f;
        #pragma unroll
        for (int nt = 0; nt < 4; nt++) {
            const int cn = bx * 128 + wn * 32 + nt * 8 + (lane & 3) * 2;
            const float2 bo = *(const float2*)&bout[cn];
            float l0 = acc[mt][nt][0] + bo.x;
            float l1 = acc[mt][nt][1] + bo.y;
            float l2 = acc[mt][nt][2] + bo.x;
            float l3 = acc[mt][nt][3] + bo.y;
            s0 += __expf(l0) + __expf(l1);
            s1 += __expf(l2) + __expf(l3);
            if (cn == tg0)     atomicAdd(&g_tgt[r0], l0);
            if (cn + 1 == tg0) atomicAdd(&g_tgt[r0], l1);
            if (cn == tg1)     atomicAdd(&g_tgt[r1], l2);
            if (cn + 1 == tg1) atomicAdd(&g_tgt[r1], l3);
        }
        s0 += __shfl_xor_sync(0xffffffffu, s0, 1);
        s0 += __shfl_xor_sync(0xffffffffu, s0, 2);
        s1 += __shfl_xor_sync(0xffffffffu, s1, 1);
        s1 += __shfl_xor_sync(0xffffffffu, s1, 2);
        if (!(lane & 3)) {
            atomicAdd(&g_sumexp[r0], s0);
            atomicAdd(&g_sumexp[r1], s1);
        }
    }
}

// ---------------- final reduction ----------------
__global__ __launch_bounds__(256) void finalize_kernel(float* out) {
    __shared__ float sm[256];
    float s = 0.f;
    for (int r = threadIdx.x; r < ROWS_; r += 256)
        s += logf(g_sumexp[r]) - g_tgt[r];
    sm[threadIdx.x] = s;
    __syncthreads();
    for (int st = 128; st; st >>= 1) {
        if (threadIdx.x < st) sm[threadIdx.x] += sm[threadIdx.x + st];
        __syncthreads();
    }
    if (threadIdx.x == 0) out[0] = sm[0] / 32.f;
}

// ---------------- host launcher ----------------
extern "C" void kernel_launch(void* const* d_in, const int* in_sizes, int n_in,
                              void* d_out, int out_size)
{
    (void)in_sizes; (void)n_in; (void)out_size;
    const int*   x        = (const int*)  d_in[0];
    const int*   y        = (const int*)  d_in[1];
    const float* encemb   = (const float*)d_in[2];
    const float* decemb   = (const float*)d_in[3];
    const float* enc_Wih0 = (const float*)d_in[4];
    const float* enc_Whh0 = (const float*)d_in[5];
    const float* enc_bih0 = (const float*)d_in[6];
    const float* enc_bhh0 = (const float*)d_in[7];
    const float* enc_Wih1 = (const float*)d_in[8];
    const float* enc_Whh1 = (const float*)d_in[9];
    const float* enc_bih1 = (const float*)d_in[10];
    const float* enc_bhh1 = (const float*)d_in[11];
    const float* dec_Wih0 = (const float*)d_in[12];
    const float* dec_Whh0 = (const float*)d_in[13];
    const float* dec_bih0 = (const float*)d_in[14];
    const float* dec_bhh0 = (const float*)d_in[15];
    const float* dec_Wih1 = (const float*)d_in[16];
    const float* dec_Whh1 = (const float*)d_in[17];
    const float* dec_bih1 = (const float*)d_in[18];
    const float* dec_bhh1 = (const float*)d_in[19];
    const float* Wout     = (const float*)d_in[20];
    const float* bout     = (const float*)d_in[21];
    float* out = (float*)d_out;

    const int DUAL_SMEM = 2 * B_ * SROW_ * 2;   // 68608
    const int CE_SMEM   = 64 * SROW_ * 2;       // 68608
    cudaFuncSetAttribute(dual_mma, cudaFuncAttributeMaxDynamicSharedMemorySize, DUAL_SMEM);
    cudaFuncSetAttribute(ce_mma,   cudaFuncAttributeMaxDynamicSharedMemorySize, CE_SMEM);

    init_kernel<<<512, 256>>>();

    const int GCONV = (NPAD_ * NK_ + 255) / 256;
    conv_gate<<<GCONV, 256>>>(enc_Whh0, 0);
    conv_gate<<<GCONV, 256>>>(enc_Wih1, 1);
    conv_gate<<<GCONV, 256>>>(enc_Whh1, 2);
    conv_gate<<<GCONV, 256>>>(dec_Whh0, 3);
    conv_gate<<<GCONV, 256>>>(dec_Wih1, 4);
    conv_gate<<<GCONV, 256>>>(dec_Whh1, 5);
    conv_wout<<<(V_ * NK_ + 255) / 256, 256>>>(Wout);
    bias_kernel<<<(2 * G4_ + 255) / 256, 256>>>(enc_bih1, enc_bhh1, dec_bih1, dec_bhh1);

    pre_kernel<<<dim3(129, 64), 128>>>(x, encemb, enc_Wih0, enc_bih0, enc_bhh0, 0);
    pre_kernel<<<dim3(129, 64), 128>>>(y, decemb, dec_Wih0, dec_bih0, dec_bhh0, 1);

    // sequential scan: slot s runs layer1(step s-1) and layer0(step s)
    for (int s = 0; s <= 128; s++) {
        Dual2 d;
        d.s0 = StepArgs{0,0,0,0,0,0};
        d.s1 = StepArgs{0,0,0,0,0,0};
        if (s >= 1) {                 // layer1 of step z = s-1
            int z = s - 1;
            int sel = (z < 64) ? 0 : 1;
            d.s0.layer  = 1;
            d.s0.sel    = sel;
            d.s0.parity = z & 1;
            d.s0.tstep  = sel ? (z - 64) : z;
            d.s0.hist   = (z >= 64) ? 1 : 0;
            d.s0.valid  = 1;
        }
        if (s <= 127) {               // layer0 of step s
            int sel = (s < 64) ? 0 : 1;
            d.s1.layer  = 0;
            d.s1.sel    = sel;
            d.s1.parity = s & 1;
            d.s1.tstep  = sel ? (s - 64) : s;
            d.s1.hist   = 0;
            d.s1.valid  = 1;
        }
        dual_mma<<<dim3(33, 2), 256, DUAL_SMEM>>>(d);
    }

    ce_mma<<<dim3(250, 32), 256, CE_SMEM>>>(y, bout);

    finalize_kernel<<<1, 256>>>(out);
}

// round 5
// speedup vs baseline: 4.0732x; 1.5930x over previous
#include <cuda_runtime.h>
#include <cuda_bf16.h>
#include <math.h>

#define B_    32
#define EMB_  256
#define HID_  516
#define G4_   2064     // 4*HID_
#define V_    32000
#define ROWS_ 2048     // 64*32 decoder rows
#define NK_   528      // K padded to multiple of 16
#define NK2_  264      // NK_/2 (u32 units)
#define NKI_  33       // k-iterations of 16
#define SROW_ 536      // smem row stride (u16) for K=528 tiles (ldmatrix conflict-free)
#define XROW_ 264      // smem row stride (u16) for K=256 tiles
#define NPAD_ 2112     // gate-col dim padded (66 tiles * 32)
#define SCAN_BLOCKS_ 132
#define CCH_  24       // CE B-chunk row stride (u16)

// ---------------- scratch (static device globals; no allocation) ----------------
__device__ __nv_bfloat16 g_Wb[6][NPAD_ * NK_];        // scan weights bf16, gate-interleaved [j*4+g][k]
__device__ __nv_bfloat16 g_Wxb[2][NPAD_ * EMB_];      // Wih0 enc/dec bf16 interleaved (K=256)
__device__ __nv_bfloat16 g_Woutb[V_ * NK_];           // Wout bf16 padded
__device__ __nv_bfloat16 g_xb[2][ROWS_ * EMB_];       // gathered embeddings bf16 [t*32+b][k]
__device__ float         g_pre[2][ROWS_ * G4_];       // input proj + bias, gate-interleaved
__device__ __nv_bfloat16 g_hb[2][2][B_ * NK_];        // h state [layer][buf], bf16 k-padded
__device__ float         g_c[2][B_ * HID_];           // c state fp32
__device__ __nv_bfloat16 g_histb[ROWS_ * NK_];        // decoder h1 history bf16
__device__ float         g_biasI0[2][G4_];            // layer0 bias (folded into pre)
__device__ float         g_biasI1[2][G4_];            // layer1 bias
__device__ float         g_sumexp[ROWS_];
__device__ float         g_tgt[ROWS_];
__device__ unsigned      g_cnt;                       // grid barrier arrivals (monotonic)
__device__ unsigned      g_rel;                       // grid barrier release step

// ---------------- helpers ----------------
__device__ __forceinline__ unsigned smem_u32(const void* p) {
    return (unsigned)__cvta_generic_to_shared(p);
}
__device__ __forceinline__ void ldsm4(unsigned a[4], unsigned addr) {
    asm volatile("ldmatrix.sync.aligned.m8n8.x4.shared.b16 {%0,%1,%2,%3}, [%4];"
        : "=r"(a[0]), "=r"(a[1]), "=r"(a[2]), "=r"(a[3]) : "r"(addr));
}
__device__ __forceinline__ void mma_bf16(float c[4], const unsigned a[4], unsigned b0, unsigned b1) {
    asm volatile("mma.sync.aligned.m16n8k16.row.col.f32.bf16.bf16.f32 "
        "{%0,%1,%2,%3},{%4,%5,%6,%7},{%8,%9},{%0,%1,%2,%3};"
        : "+f"(c[0]), "+f"(c[1]), "+f"(c[2]), "+f"(c[3])
        : "r"(a[0]), "r"(a[1]), "r"(a[2]), "r"(a[3]), "r"(b0), "r"(b1));
}
__device__ __forceinline__ float sigf(float x) { return 1.f / (1.f + __expf(-x)); }

// ---------------- init ----------------
__global__ void init_kernel() {
    const int stride = gridDim.x * blockDim.x;
    const int i0 = blockIdx.x * blockDim.x + threadIdx.x;
    const __nv_bfloat16 z = __float2bfloat16(0.f);
    for (int i = i0; i < B_ * NK_; i += stride) {
        g_hb[0][0][i] = z; g_hb[0][1][i] = z;
        g_hb[1][0][i] = z; g_hb[1][1][i] = z;
    }
    for (int i = i0; i < B_ * HID_; i += stride) { g_c[0][i] = 0.f; g_c[1][i] = 0.f; }
    for (int i = i0; i < ROWS_; i += stride)     { g_sumexp[i] = 0.f; g_tgt[i] = 0.f; }
    for (int i = i0; i < ROWS_ * NK_; i += stride) g_histb[i] = z;
    if (blockIdx.x == 0 && threadIdx.x == 0) { g_cnt = 0u; g_rel = 0u; }
}

// ---------------- weight conversions ----------------
__global__ __launch_bounds__(256) void conv_gate(const float* __restrict__ src, int slot) {
    int idx = blockIdx.x * blockDim.x + threadIdx.x;   // over NPAD_*264 (u32 pairs)
    if (idx >= NPAD_ * NK2_) return;
    int n = idx / NK2_, q = idx - n * NK2_, k = q * 2;
    float2 v = make_float2(0.f, 0.f);
    if (n < G4_ && k < HID_) {
        int j = n >> 2, g = n & 3;
        v = *(const float2*)&src[(size_t)(g * HID_ + j) * HID_ + k];
    }
    unsigned o = ((unsigned)__bfloat16_as_ushort(__float2bfloat16(v.y)) << 16)
               |  (unsigned)__bfloat16_as_ushort(__float2bfloat16(v.x));
    *(unsigned*)&g_Wb[slot][n * NK_ + k] = o;
}

__global__ __launch_bounds__(256) void conv_gate_x(const float* __restrict__ src, int slot) {
    int idx = blockIdx.x * blockDim.x + threadIdx.x;   // over NPAD_*128
    if (idx >= NPAD_ * (EMB_ / 2)) return;
    int n = idx / (EMB_ / 2), q = idx - n * (EMB_ / 2), k = q * 2;
    float2 v = make_float2(0.f, 0.f);
    if (n < G4_) {
        int j = n >> 2, g = n & 3;
        v = *(const float2*)&src[(size_t)(g * HID_ + j) * EMB_ + k];
    }
    unsigned o = ((unsigned)__bfloat16_as_ushort(__float2bfloat16(v.y)) << 16)
               |  (unsigned)__bfloat16_as_ushort(__float2bfloat16(v.x));
    *(unsigned*)&g_Wxb[slot][n * EMB_ + k] = o;
}

__global__ __launch_bounds__(256) void conv_wout(const float* __restrict__ src) {
    int idx = blockIdx.x * blockDim.x + threadIdx.x;   // over V_*132 (float4 quads)
    if (idx >= V_ * (NK_ / 4)) return;
    int n = idx / (NK_ / 4), q = idx - n * (NK_ / 4), k = q * 4;
    float4 v = make_float4(0.f, 0.f, 0.f, 0.f);
    if (k < HID_) v = *(const float4*)&src[(size_t)n * HID_ + k];
    ushort4 o;
    o.x = __bfloat16_as_ushort(__float2bfloat16(v.x));
    o.y = __bfloat16_as_ushort(__float2bfloat16(v.y));
    o.z = __bfloat16_as_ushort(__float2bfloat16(v.z));
    o.w = __bfloat16_as_ushort(__float2bfloat16(v.w));
    *(ushort4*)&g_Woutb[(size_t)n * NK_ + k] = o;
}

__global__ __launch_bounds__(256) void bias_kernel(
    const float* eb0a, const float* eb0b, const float* db0a, const float* db0b,
    const float* eb1a, const float* eb1b, const float* db1a, const float* db1b)
{
    int t = blockIdx.x * blockDim.x + threadIdx.x;
    if (t >= 2 * G4_) return;
    int sel = t / G4_, n = t - sel * G4_;
    int j = n >> 2, g = n & 3;
    g_biasI0[sel][n] = (sel ? db0a : eb0a)[g * HID_ + j] + (sel ? db0b : eb0b)[g * HID_ + j];
    g_biasI1[sel][n] = (sel ? db1a : eb1a)[g * HID_ + j] + (sel ? db1b : eb1b)[g * HID_ + j];
}

// ---------------- embedding gather -> bf16 ----------------
__global__ __launch_bounds__(256) void gather_x(const int* __restrict__ x,
                                                const int* __restrict__ y,
                                                const float* __restrict__ encemb,
                                                const float* __restrict__ decemb)
{
    const int row = blockIdx.x;           // 0..2047 (= t*32+b)
    const int which = blockIdx.y;
    const int tok = which ? y[row] : x[row];
    const float* emb = which ? decemb : encemb;
    const int k = threadIdx.x;            // 256
    g_xb[which][row * EMB_ + k] = __float2bfloat16(emb[(size_t)tok * EMB_ + k]);
}

// ---------------- input projection GEMM: pre = xb @ Wih0^T + bias (bf16 mma) ----------------
// grid (33, 32): bx = N-tile of 64; by: which = by>>4, mtile = by&15 (M=128).
__global__ __launch_bounds__(256) void pre_gemm() {
    extern __shared__ __align__(16) unsigned short psm[];
    unsigned short* sA = psm;                       // [128][XROW_]
    unsigned short* sB = psm + 128 * XROW_;         // [64][XROW_]
    const int tid = threadIdx.x, lane = tid & 31, warp = tid >> 5;
    const int which = blockIdx.y >> 4, mtile = blockIdx.y & 15;
    const int m0 = mtile * 128, n0 = blockIdx.x * 64;

    // stage A (128 x 256 bf16) and B (64 x 256 bf16)
    {
        const uint2* srcA = (const uint2*)(g_xb[which] + (size_t)m0 * EMB_);
        uint2* dA = (uint2*)sA;
        int r = tid >> 1;
        #pragma unroll
        for (int k = (tid & 1); k < 64; k += 2) dA[r * (XROW_ / 4) + k] = srcA[r * 64 + k];
        const uint2* srcB = (const uint2*)(g_Wxb[which] + (size_t)n0 * EMB_);
        uint2* dB = (uint2*)sB;
        int rb = tid >> 2;
        #pragma unroll
        for (int k = (tid & 3); k < 64; k += 4) dB[rb * (XROW_ / 4) + k] = srcB[rb * 64 + k];
    }
    __syncthreads();

    const int wm = warp >> 2, wn = warp & 3;   // 2 x 4
    float acc[4][2][4];
    #pragma unroll
    for (int a = 0; a < 4; a++) for (int b = 0; b < 2; b++) for (int r = 0; r < 4; r++)
        acc[a][b][r] = 0.f;

    const unsigned sbA = smem_u32(sA);
    const unsigned a_off =
        (((unsigned)((lane & 7) + ((lane >> 3) & 1) * 8)) * XROW_ + (unsigned)(lane >> 4) * 8) * 2;
    const unsigned short* brow = sB + (wn * 16 + (lane >> 2)) * XROW_ + (lane & 3) * 2;

    #pragma unroll 4
    for (int ki = 0; ki < 16; ki++) {
        const int k0 = ki * 16;
        unsigned av[4][4];
        #pragma unroll
        for (int mt = 0; mt < 4; mt++)
            ldsm4(av[mt], sbA + a_off + (unsigned)((wm * 64 + mt * 16) * XROW_ + k0) * 2);
        #pragma unroll
        for (int nt = 0; nt < 2; nt++) {
            unsigned b0 = *(const unsigned*)(brow + nt * 8 * XROW_ + k0);
            unsigned b1 = *(const unsigned*)(brow + nt * 8 * XROW_ + k0 + 8);
            #pragma unroll
            for (int mt = 0; mt < 4; mt++) mma_bf16(acc[mt][nt], av[mt], b0, b1);
        }
    }

    float ex[4][2][4];
    #pragma unroll
    for (int a = 0; a < 4; a++) for (int b = 0; b < 2; b++) for (int r = 0; r < 4; r++)
        ex[a][b][r] = __shfl_xor_sync(0xffffffffu, acc[a][b][r], 1);

    if (!(lane & 1)) {
        #pragma unroll
        for (int mt = 0; mt < 4; mt++) {
            #pragma unroll
            for (int nt = 0; nt < 2; nt++) {
                const int cn = n0 + wn * 16 + nt * 8 + (lane & 3) * 2;
                if (cn >= G4_) continue;
                const float4 bi = *(const float4*)&g_biasI0[which][cn];
                #pragma unroll
                for (int half = 0; half < 2; half++) {
                    const int row = m0 + wm * 64 + mt * 16 + half * 8 + (lane >> 2);
                    float4 o4;
                    o4.x = acc[mt][nt][half * 2 + 0] + bi.x;
                    o4.y = acc[mt][nt][half * 2 + 1] + bi.y;
                    o4.z = ex[mt][nt][half * 2 + 0] + bi.z;
                    o4.w = ex[mt][nt][half * 2 + 1] + bi.w;
                    *(float4*)&g_pre[which][(size_t)row * G4_ + cn] = o4;
                }
            }
        }
    }
}

// ---------------- persistent scan kernel with grid barrier ----------------
__device__ __forceinline__ void gbar(int step) {
    __syncthreads();
    if (threadIdx.x == 0) {
        __threadfence();
        unsigned arrived = atomicAdd(&g_cnt, 1u) + 1u;
        unsigned target = (unsigned)SCAN_BLOCKS_ * (unsigned)(step + 1);
        if (arrived == target) {
            asm volatile("st.release.gpu.global.u32 [%0], %1;"
                :: "l"(&g_rel), "r"((unsigned)(step + 1)) : "memory");
        } else {
            unsigned v;
            do {
                asm volatile("ld.acquire.gpu.global.u32 %0, [%1];"
                    : "=r"(v) : "l"(&g_rel) : "memory");
                if (v < (unsigned)(step + 1)) __nanosleep(32);
            } while (v < (unsigned)(step + 1));
        }
    }
    __syncthreads();
}

// 132 blocks x 128 threads. bid<66: layer0 tile; else layer1 tile. N-tile = 32 gate-cols.
__global__ __launch_bounds__(128) void scan_kernel() {
    extern __shared__ __align__(16) unsigned short ssm[];
    unsigned short* sA = ssm;                    // 2 segs x [32][SROW_]
    unsigned short* sW = ssm + 2 * 32 * SROW_;   // 2 segs x [32][SROW_]
    const int bid = blockIdx.x;
    const int layer = (bid >= 66) ? 1 : 0;
    const int tile = layer ? bid - 66 : bid;
    const int tid = threadIdx.x, lane = tid & 31, warp = tid >> 5;
    const int nseg = layer ? 2 : 1;
    const int nw = tile * 32 + warp * 8;
    int cur_sel = -1;

    const unsigned sbA = smem_u32(sA);
    const unsigned a_off =
        (((unsigned)((lane & 7) + ((lane >> 3) & 1) * 8)) * SROW_ + (unsigned)(lane >> 4) * 8) * 2;

    for (int s = 0; s <= 128; s++) {
        const int t = layer ? s - 1 : s;
        const bool active = layer ? (s >= 1) : (s <= 127);
        if (active) {
            const int sel = (t >= 64) ? 1 : 0;
            const int p = t & 1;
            const int tstep = sel ? t - 64 : t;

            if (sel != cur_sel) {  // load this phase's weight slice(s) into smem
                cur_sel = sel;
                for (int sg = 0; sg < nseg; sg++) {
                    const int slot = sel * 3 + (layer ? 1 + sg : 0);
                    const uint2* src = (const uint2*)(g_Wb[slot] + (size_t)tile * 32 * NK_);
                    uint2* dst = (uint2*)(sW + sg * 32 * SROW_);
                    int r = tid >> 2;
                    #pragma unroll
                    for (int k = (tid & 3); k < NK2_ / 2; k += 4)
                        dst[r * (SROW_ / 4) + k] = src[r * (NK2_ / 2) + k];
                }
            }
            // stage A (h vectors)
            {
                const uint2* a0 = (const uint2*)(layer ? g_hb[0][p ^ 1] : g_hb[0][p]);
                const uint2* a1 = (const uint2*)(layer ? g_hb[1][p] : g_hb[0][p]);
                for (int sg = 0; sg < nseg; sg++) {
                    const uint2* src = sg ? a1 : a0;
                    uint2* dst = (uint2*)(sA + sg * 32 * SROW_);
                    int r = tid >> 2;
                    #pragma unroll
                    for (int k = (tid & 3); k < NK2_ / 2; k += 4)
                        dst[r * (SROW_ / 4) + k] = src[r * (NK2_ / 2) + k];
                }
            }
            __syncthreads();

            float acc[2][4] = {{0.f,0.f,0.f,0.f},{0.f,0.f,0.f,0.f}};
            for (int sg = 0; sg < nseg; sg++) {
                const unsigned short* wrow = sW + sg * 32 * SROW_
                    + (warp * 8 + (lane >> 2)) * SROW_ + (lane & 3) * 2;
                const unsigned abase = sbA + (unsigned)sg * 32 * SROW_ * 2 + a_off;
                #pragma unroll 4
                for (int ki = 0; ki < NKI_; ki++) {
                    const int k0 = ki * 16;
                    unsigned av0[4], av1[4];
                    ldsm4(av0, abase + (unsigned)k0 * 2);
                    ldsm4(av1, abase + (unsigned)(16 * SROW_ + k0) * 2);
                    unsigned b0 = *(const unsigned*)(wrow + k0);
                    unsigned b1 = *(const unsigned*)(wrow + k0 + 8);
                    mma_bf16(acc[0], av0, b0, b1);
                    mma_bf16(acc[1], av1, b0, b1);
                }
            }

            float ex[2][4];
            #pragma unroll
            for (int mt = 0; mt < 2; mt++)
                #pragma unroll
                for (int r = 0; r < 4; r++)
                    ex[mt][r] = __shfl_xor_sync(0xffffffffu, acc[mt][r], 1);

            const int cn = nw + (lane & 3) * 2;
            if (!(lane & 1) && cn < G4_) {
                const int j = cn >> 2;
                float* cst = g_c[layer];
                __nv_bfloat16* hout = g_hb[layer][p ^ 1];
                #pragma unroll
                for (int mt = 0; mt < 2; mt++) {
                    #pragma unroll
                    for (int half = 0; half < 2; half++) {
                        const int b = (lane >> 2) + mt * 16 + half * 8;
                        const float ip = acc[mt][half * 2 + 0];
                        const float fp = acc[mt][half * 2 + 1];
                        const float gp = ex[mt][half * 2 + 0];
                        const float op = ex[mt][half * 2 + 1];
                        float4 add = layer
                            ? *(const float4*)&g_biasI1[sel][cn]
                            : *(const float4*)&g_pre[sel][(size_t)(tstep * B_ + b) * G4_ + cn];
                        float iv = sigf(ip + add.x);
                        float fv = sigf(fp + add.y);
                        float gv = tanhf(gp + add.z);
                        float ov = sigf(op + add.w);
                        float c = cst[b * HID_ + j];
                        c = fv * c + iv * gv;
                        cst[b * HID_ + j] = c;
                        float h = ov * tanhf(c);
                        __nv_bfloat16 hb = __float2bfloat16(h);
                        hout[b * NK_ + j] = hb;
                        if (layer && sel) g_histb[(size_t)(tstep * B_ + b) * NK_ + j] = hb;
                    }
                }
            }
        }
        if (s < 128) gbar(s);
    }
}

// ---------------- fused vocab projection + CE (bf16 mma, cp.async B chunks) ----------------
// grid (250, 16), 256 thr. Block tile M=128 x N=128. Warps: wm 0..1 (M=64), wn 0..3 (N=32).
__global__ __launch_bounds__(256) void ce_mma(const int* __restrict__ y,
                                              const float* __restrict__ bout) {
    extern __shared__ __align__(16) unsigned short csm[];
    unsigned short* sA = csm;                      // [128][SROW_]
    unsigned short* sB = csm + 128 * SROW_;        // 2 x [128][CCH_]
    const int tid = threadIdx.x, lane = tid & 31, warp = tid >> 5;
    const int bx = blockIdx.x, by = blockIdx.y;

    // stage A (128 hist rows)
    {
        const uint2* src = (const uint2*)(g_histb + (size_t)by * 128 * NK_);
        uint2* dst = (uint2*)sA;
        int r = tid >> 1;
        #pragma unroll
        for (int k = (tid & 1); k < NK2_ / 2; k += 2)
            dst[r * (SROW_ / 4) + k] = src[r * (NK2_ / 2) + k];
    }

    // cp.async chunk staging: thread t -> row t>>1, half t&1 (16B each)
    const char* gB = (const char*)(g_Woutb + (size_t)(bx * 128 + (tid >> 1)) * NK_ + (tid & 1) * 8);
    unsigned dB = smem_u32(sB) + (unsigned)((tid >> 1) * CCH_ + (tid & 1) * 8) * 2;
    const unsigned bufstride = 128 * CCH_ * 2;

    #define STAGE(KI) do { \
        unsigned d = dB + (unsigned)((KI) & 1) * bufstride; \
        const char* s = gB + (size_t)(KI) * 32; \
        asm volatile("cp.async.cg.shared.global [%0], [%1], 16;" :: "r"(d), "l"(s)); \
        asm volatile("cp.async.commit_group;"); \
    } while (0)

    STAGE(0);

    const int wm = warp >> 2, wn = warp & 3;
    float acc[4][4][4];
    #pragma unroll
    for (int a = 0; a < 4; a++) for (int b = 0; b < 4; b++) for (int r = 0; r < 4; r++)
        acc[a][b][r] = 0.f;

    const unsigned sbA = smem_u32(sA);
    const unsigned a_off =
        (((unsigned)((lane & 7) + ((lane >> 3) & 1) * 8)) * SROW_ + (unsigned)(lane >> 4) * 8) * 2;

    for (int ki = 0; ki < NKI_; ki++) {
        if (ki + 1 < NKI_) {
            STAGE(ki + 1);
            asm volatile("cp.async.wait_group 1;");
        } else {
            asm volatile("cp.async.wait_group 0;");
        }
        __syncthreads();

        const int k0 = ki * 16;
        unsigned av[4][4];
        #pragma unroll
        for (int mt = 0; mt < 4; mt++)
            ldsm4(av[mt], sbA + a_off + (unsigned)((wm * 64 + mt * 16) * SROW_ + k0) * 2);
        const unsigned short* brow = sB + (ki & 1) * 128 * CCH_
            + (wn * 32 + (lane >> 2)) * CCH_ + (lane & 3) * 2;
        #pragma unroll
        for (int nt = 0; nt < 4; nt++) {
            unsigned b0 = *(const unsigned*)(brow + nt * 8 * CCH_);
            unsigned b1 = *(const unsigned*)(brow + nt * 8 * CCH_ + 8);
            #pragma unroll
            for (int mt = 0; mt < 4; mt++) mma_bf16(acc[mt][nt], av[mt], b0, b1);
        }
        __syncthreads();
    }
    #undef STAGE

    // epilogue: per-row sum(exp(logit)) + target logit
    #pragma unroll
    for (int mt = 0; mt < 4; mt++) {
        const int r0 = by * 128 + wm * 64 + mt * 16 + (lane >> 2);
        const int r1 = r0 + 8;
        const int tg0 = y[r0 + 32];
        const int tg1 = y[r1 + 32];
        float s0 = 0.f, s1 = 0.f;
        #pragma unroll
        for (int nt = 0; nt < 4; nt++) {
            const int cn = bx * 128 + wn * 32 + nt * 8 + (lane & 3) * 2;
            const float2 bo = *(const float2*)&bout[cn];
            float l0 = acc[mt][nt][0] + bo.x;
            float l1 = acc[mt][nt][1] + bo.y;
            float l2 = acc[mt][nt][2] + bo.x;
            float l3 = acc[mt][nt][3] + bo.y;
            s0 += __expf(l0) + __expf(l1);
            s1 += __expf(l2) + __expf(l3);
            if (cn == tg0)     atomicAdd(&g_tgt[r0], l0);
            if (cn + 1 == tg0) atomicAdd(&g_tgt[r0], l1);
            if (cn == tg1)     atomicAdd(&g_tgt[r1], l2);
            if (cn + 1 == tg1) atomicAdd(&g_tgt[r1], l3);
        }
        s0 += __shfl_xor_sync(0xffffffffu, s0, 1);
        s0 += __shfl_xor_sync(0xffffffffu, s0, 2);
        s1 += __shfl_xor_sync(0xffffffffu, s1, 1);
        s1 += __shfl_xor_sync(0xffffffffu, s1, 2);
        if (!(lane & 3)) {
            atomicAdd(&g_sumexp[r0], s0);
            atomicAdd(&g_sumexp[r1], s1);
        }
    }
}

// ---------------- final reduction ----------------
__global__ __launch_bounds__(256) void finalize_kernel(float* out) {
    __shared__ float sm[256];
    float s = 0.f;
    for (int r = threadIdx.x; r < ROWS_; r += 256)
        s += logf(g_sumexp[r]) - g_tgt[r];
    sm[threadIdx.x] = s;
    __syncthreads();
    for (int st = 128; st; st >>= 1) {
        if (threadIdx.x < st) sm[threadIdx.x] += sm[threadIdx.x + st];
        __syncthreads();
    }
    if (threadIdx.x == 0) out[0] = sm[0] / 32.f;
}

// ---------------- host launcher ----------------
extern "C" void kernel_launch(void* const* d_in, const int* in_sizes, int n_in,
                              void* d_out, int out_size)
{
    (void)in_sizes; (void)n_in; (void)out_size;
    const int*   x        = (const int*)  d_in[0];
    const int*   y        = (const int*)  d_in[1];
    const float* encemb   = (const float*)d_in[2];
    const float* decemb   = (const float*)d_in[3];
    const float* enc_Wih0 = (const float*)d_in[4];
    const float* enc_Whh0 = (const float*)d_in[5];
    const float* enc_bih0 = (const float*)d_in[6];
    const float* enc_bhh0 = (const float*)d_in[7];
    const float* enc_Wih1 = (const float*)d_in[8];
    const float* enc_Whh1 = (const float*)d_in[9];
    const float* enc_bih1 = (const float*)d_in[10];
    const float* enc_bhh1 = (const float*)d_in[11];
    const float* dec_Wih0 = (const float*)d_in[12];
    const float* dec_Whh0 = (const float*)d_in[13];
    const float* dec_bih0 = (const float*)d_in[14];
    const float* dec_bhh0 = (const float*)d_in[15];
    const float* dec_Wih1 = (const float*)d_in[16];
    const float* dec_Whh1 = (const float*)d_in[17];
    const float* dec_bih1 = (const float*)d_in[18];
    const float* dec_bhh1 = (const float*)d_in[19];
    const float* Wout     = (const float*)d_in[20];
    const float* bout     = (const float*)d_in[21];
    float* out = (float*)d_out;

    const int PRE_SMEM  = (128 + 64) * XROW_ * 2;                 // 101,376
    const int SCAN_SMEM = 4 * 32 * SROW_ * 2;                     // 137,216
    const int CE_SMEM   = 128 * SROW_ * 2 + 2 * 128 * CCH_ * 2;   // 149,504
    cudaFuncSetAttribute(pre_gemm,    cudaFuncAttributeMaxDynamicSharedMemorySize, PRE_SMEM);
    cudaFuncSetAttribute(scan_kernel, cudaFuncAttributeMaxDynamicSharedMemorySize, SCAN_SMEM);
    cudaFuncSetAttribute(ce_mma,      cudaFuncAttributeMaxDynamicSharedMemorySize, CE_SMEM);

    init_kernel<<<512, 256>>>();

    const int GC = (NPAD_ * NK2_ + 255) / 256;
    conv_gate<<<GC, 256>>>(enc_Whh0, 0);
    conv_gate<<<GC, 256>>>(enc_Wih1, 1);
    conv_gate<<<GC, 256>>>(enc_Whh1, 2);
    conv_gate<<<GC, 256>>>(dec_Whh0, 3);
    conv_gate<<<GC, 256>>>(dec_Wih1, 4);
    conv_gate<<<GC, 256>>>(dec_Whh1, 5);
    const int GX = (NPAD_ * (EMB_ / 2) + 255) / 256;
    conv_gate_x<<<GX, 256>>>(enc_Wih0, 0);
    conv_gate_x<<<GX, 256>>>(dec_Wih0, 1);
    conv_wout<<<(V_ * (NK_ / 4) + 255) / 256, 256>>>(Wout);
    bias_kernel<<<(2 * G4_ + 255) / 256, 256>>>(enc_bih0, enc_bhh0, dec_bih0, dec_bhh0,
                                                enc_bih1, enc_bhh1, dec_bih1, dec_bhh1);

    gather_x<<<dim3(ROWS_, 2), EMB_>>>(x, y, encemb, decemb);
    pre_gemm<<<dim3(33, 32), 256, PRE_SMEM>>>();

    scan_kernel<<<SCAN_BLOCKS_, 128, SCAN_SMEM>>>();

    ce_mma<<<dim3(250, 16), 256, CE_SMEM>>>(y, bout);

    finalize_kernel<<<1, 256>>>(out);
}